// round 4
// baseline (speedup 1.0000x reference)
#include <cuda_runtime.h>
#include <cstdint>

// ---------------------------------------------------------------------------
// Fused recurrent decoder: B=32768 rows, T=30 steps, D=384, FF=1024, HID=64.
// One block = 64 rows, all 30 steps. TF32 mma.sync for the 4 big GEMMs,
// fp32 for the tiny decoder tail. Weights stream from L2 each step.
// ---------------------------------------------------------------------------

#define B_TOTAL   32768
#define T_STEPS   30
#define D_DIM     384
#define FF_DIM    1024
#define M_ROWS    64
#define NTHREADS  256

#define LDA   388   // xs row stride   (388 % 32 == 4 -> conflict-free frags)
#define LDY   68    // ych row stride
#define LDC   68    // consumer weight tile row stride
#define LDK   196   // producer weight tile row stride

// shared memory float offsets
#define XS     0                 // 64*388 = 24832
#define YCH    24832             // 64*68  = 4352
#define BT     29184             // 13056 (max of 64*196=12544, 192*68=13056)
#define WP_    42240             // 1152
#define WS_    43392             // 1152
#define BP_    44544             // 384
#define BS_    44928             // 384
#define BV_    45312             // 384
#define BO_    45696             // 384
#define B1_    46080             // 1024
#define B2_    47104             // 384
#define G1_    47488             // 384
#define BE1_   47872             // 384
#define G2_    48256             // 384
#define BE2_   48640             // 384
#define BD1_   49024             // 64
#define WD2_   49088             // 192
#define BD2_   49280             // 4
#define GATE_  49284             // 64
#define STATE_ 49348             // 192
#define PLAN_  49540             // 192
#define RED_   49732             // 512 (float2[64][4])
#define SMEM_FLOATS 50244
#define SMEM_BYTES  (SMEM_FLOATS * 4)   // 200976

__device__ __forceinline__ uint32_t f2tf(float x) {
    uint32_t u;
    asm("cvt.rna.tf32.f32 %0, %1;" : "=r"(u) : "f"(x));
    return u;
}

__device__ __forceinline__ void mma8(float* c, uint32_t a0, uint32_t a1,
                                     uint32_t a2, uint32_t a3,
                                     uint32_t b0, uint32_t b1) {
    asm volatile(
        "mma.sync.aligned.m16n8k8.row.col.f32.tf32.tf32.f32 "
        "{%0,%1,%2,%3}, {%4,%5,%6,%7}, {%8,%9}, {%0,%1,%2,%3};"
        : "+f"(c[0]), "+f"(c[1]), "+f"(c[2]), "+f"(c[3])
        : "r"(a0), "r"(a1), "r"(a2), "r"(a3), "r"(b0), "r"(b1));
}

// ---------------------------------------------------------------------------
// Producer: ych[64 x 64] = ACT( xs[64 x 384] @ Wg[0..63][0..383]^T + bias )
// ACT: 0 none, 1 relu, 2 elu.  TF: store tf32 bit pattern (for mma consumer).
// Warp layout: wm = warp>>1 owns rows wm*16..+15, wn = warp&1 owns n-tiles
// wn*32..+31 (4 tiles of 8). Begins with __syncthreads (protects btile/xs).
// ---------------------------------------------------------------------------
template<int ACT, bool TF>
__device__ __forceinline__ void producer64(
    const float* __restrict__ Wg, const float* __restrict__ bias,
    float* __restrict__ sm, int wm, int wn, int lane, int tid)
{
    float* xs  = sm + XS;
    float* ych = sm + YCH;
    float* bt  = sm + BT;

    float pacc[16];
#pragma unroll
    for (int i = 0; i < 16; i++) pacc[i] = 0.f;

#pragma unroll
    for (int stg = 0; stg < 2; stg++) {
        __syncthreads();
        // stage Wg[64 n][192 k] as tf32 into bt (stride LDK)
#pragma unroll
        for (int i = 0; i < 12; i++) {
            int q  = tid + i * NTHREADS;       // 0..3071 float4 slots
            int n  = q / 48;
            int kq = q - n * 48;
            float4 v = *reinterpret_cast<const float4*>(Wg + n * D_DIM + stg * 192 + kq * 4);
            float4 w;
            w.x = __uint_as_float(f2tf(v.x));
            w.y = __uint_as_float(f2tf(v.y));
            w.z = __uint_as_float(f2tf(v.z));
            w.w = __uint_as_float(f2tf(v.w));
            *reinterpret_cast<float4*>(bt + n * LDK + kq * 4) = w;
        }
        __syncthreads();

        const float* ap0 = xs + (wm * 16 + (lane >> 2)) * LDA + stg * 192 + (lane & 3);
#pragma unroll 8
        for (int k8 = 0; k8 < 24; k8++) {
            const float* ap = ap0 + k8 * 8;
            uint32_t a0 = f2tf(ap[0]);
            uint32_t a1 = f2tf(ap[8 * LDA]);
            uint32_t a2 = f2tf(ap[4]);
            uint32_t a3 = f2tf(ap[8 * LDA + 4]);
#pragma unroll
            for (int tl = 0; tl < 4; tl++) {
                const float* bp = bt + (wn * 32 + tl * 8 + (lane >> 2)) * LDK + k8 * 8 + (lane & 3);
                mma8(pacc + tl * 4, a0, a1, a2, a3,
                     __float_as_uint(bp[0]), __float_as_uint(bp[4]));
            }
        }
    }

    // epilogue: bias + activation, write ych
    int r0 = wm * 16 + (lane >> 2);
    int r1 = r0 + 8;
#pragma unroll
    for (int tl = 0; tl < 4; tl++) {
        int n0 = wn * 32 + tl * 8 + ((lane & 3) << 1);
        float bb0 = bias[n0], bb1 = bias[n0 + 1];
        float v[4];
        v[0] = pacc[tl * 4 + 0] + bb0;
        v[1] = pacc[tl * 4 + 1] + bb1;
        v[2] = pacc[tl * 4 + 2] + bb0;
        v[3] = pacc[tl * 4 + 3] + bb1;
#pragma unroll
        for (int cc = 0; cc < 4; cc++) {
            float x = v[cc];
            if (ACT == 1) x = fmaxf(x, 0.f);
            if (ACT == 2) x = (x > 0.f) ? x : expm1f(x);
            v[cc] = TF ? __uint_as_float(f2tf(x)) : x;
        }
        ych[r0 * LDY + n0]     = v[0];
        ych[r0 * LDY + n0 + 1] = v[1];
        ych[r1 * LDY + n0]     = v[2];
        ych[r1 * LDY + n0 + 1] = v[3];
    }
}

// ---------------------------------------------------------------------------
// Consumer: acc[64 x 384] += ych[64 x 64] @ Wc[n=0..383][k chunk]^T
// Wc points at W + chunk*64 (column offset), row n at Wc + n*ldw.
// Warp layout: mg = warp>>2 (2 m-tiles: mg*32 + mt*16), ng = warp&3
// (n-tiles ng*16 + nt*8 within each 64-wide n-subchunk s of 6).
// acc index: ((s*2+mt)*2+nt)*4 + cc  -> 96 registers.
// ---------------------------------------------------------------------------
__device__ __forceinline__ void consumer384(
    const float* __restrict__ Wc, int ldw,
    float* __restrict__ sm, float (&acc)[96],
    int mg, int ng, int lane, int tid)
{
    float* ych = sm + YCH;
    float* bt  = sm + BT;

#pragma unroll
    for (int stg = 0; stg < 2; stg++) {
        __syncthreads();
        // stage Wc[stg*192 .. +192][0..63] as tf32 into bt (stride LDC)
#pragma unroll
        for (int i = 0; i < 12; i++) {
            int q  = tid + i * NTHREADS;       // 0..3071 float4 slots
            int n  = q >> 4;
            int kq = q & 15;
            float4 v = *reinterpret_cast<const float4*>(Wc + (size_t)(stg * 192 + n) * ldw + kq * 4);
            float4 w;
            w.x = __uint_as_float(f2tf(v.x));
            w.y = __uint_as_float(f2tf(v.y));
            w.z = __uint_as_float(f2tf(v.z));
            w.w = __uint_as_float(f2tf(v.w));
            *reinterpret_cast<float4*>(bt + n * LDC + kq * 4) = w;
        }
        __syncthreads();

#pragma unroll
        for (int k8 = 0; k8 < 8; k8++) {
            uint32_t a[2][4];
#pragma unroll
            for (int mt = 0; mt < 2; mt++) {
                const float* ap = ych + ((mg * 2 + mt) * 16 + (lane >> 2)) * LDY + k8 * 8 + (lane & 3);
                a[mt][0] = __float_as_uint(ap[0]);
                a[mt][1] = __float_as_uint(ap[8 * LDY]);
                a[mt][2] = __float_as_uint(ap[4]);
                a[mt][3] = __float_as_uint(ap[8 * LDY + 4]);
            }
#pragma unroll
            for (int sl = 0; sl < 3; sl++) {
#pragma unroll
                for (int nt = 0; nt < 2; nt++) {
                    const float* bp = bt + (sl * 64 + ng * 16 + nt * 8 + (lane >> 2)) * LDC + k8 * 8 + (lane & 3);
                    uint32_t b0 = __float_as_uint(bp[0]);
                    uint32_t b1 = __float_as_uint(bp[4]);
#pragma unroll
                    for (int mt = 0; mt < 2; mt++) {
                        const int s = stg * 3 + sl;
                        mma8(acc + ((s * 2 + mt) * 2 + nt) * 4,
                             a[mt][0], a[mt][1], a[mt][2], a[mt][3], b0, b1);
                    }
                }
            }
        }
    }
}

// ---------------------------------------------------------------------------
// LN epilogue: xs <- LN(xs + acc) * g + be   (row-wise over 384 cols)
// ---------------------------------------------------------------------------
__device__ __forceinline__ void ln_epilogue(
    float* __restrict__ sm, float (&acc)[96],
    const float* __restrict__ g, const float* __restrict__ be,
    int mg, int ng, int lane)
{
    float*  xs  = sm + XS;
    float2* red = reinterpret_cast<float2*>(sm + RED_);

    float s4[4], q4[4];
#pragma unroll
    for (int i = 0; i < 4; i++) { s4[i] = 0.f; q4[i] = 0.f; }

    // pass 1: residual add (store back) + partial sums per row
#pragma unroll
    for (int s = 0; s < 6; s++)
#pragma unroll
        for (int mt = 0; mt < 2; mt++)
#pragma unroll
            for (int nt = 0; nt < 2; nt++)
#pragma unroll
                for (int cc = 0; cc < 4; cc++) {
                    int r = mg * 32 + mt * 16 + (lane >> 2) + ((cc >> 1) << 3);
                    int n = s * 64 + ng * 16 + nt * 8 + ((lane & 3) << 1) + (cc & 1);
                    float v = xs[r * LDA + n] + acc[((s * 2 + mt) * 2 + nt) * 4 + cc];
                    xs[r * LDA + n] = v;
                    int ri = mt * 2 + (cc >> 1);
                    s4[ri] += v;
                    q4[ri] += v * v;
                }
    // reduce over the 4 lanes (lane&3) that share each row
#pragma unroll
    for (int d = 1; d < 4; d <<= 1)
#pragma unroll
        for (int i = 0; i < 4; i++) {
            s4[i] += __shfl_xor_sync(0xffffffffu, s4[i], d);
            q4[i] += __shfl_xor_sync(0xffffffffu, q4[i], d);
        }
    if ((lane & 3) == 0) {
#pragma unroll
        for (int i = 0; i < 4; i++) {
            int r = mg * 32 + (i >> 1) * 16 + (lane >> 2) + ((i & 1) << 3);
            red[r * 4 + ng] = make_float2(s4[i], q4[i]);
        }
    }
    __syncthreads();

    // pass 2: normalize + affine
#pragma unroll
    for (int i = 0; i < 4; i++) {
        int mt = i >> 1, h = i & 1;
        int r = mg * 32 + mt * 16 + (lane >> 2) + h * 8;
        float S = 0.f, Q = 0.f;
#pragma unroll
        for (int w = 0; w < 4; w++) { float2 tv = red[r * 4 + w]; S += tv.x; Q += tv.y; }
        float m   = S * (1.f / 384.f);
        float var = Q * (1.f / 384.f) - m * m;
        float rs  = rsqrtf(var + 1e-5f);
#pragma unroll
        for (int s = 0; s < 6; s++)
#pragma unroll
            for (int nt = 0; nt < 2; nt++)
#pragma unroll
                for (int cc = 0; cc < 2; cc++) {
                    int n = s * 64 + ng * 16 + nt * 8 + ((lane & 3) << 1) + cc;
                    float v = xs[r * LDA + n];
                    xs[r * LDA + n] = (v - m) * rs * g[n] + be[n];
                }
    }
}

__device__ __forceinline__ void cpy(float* __restrict__ dst,
                                    const float* __restrict__ src,
                                    int n, int tid)
{
    for (int i = tid; i < n; i += NTHREADS) dst[i] = src[i];
}

// ---------------------------------------------------------------------------
// Main kernel
// ---------------------------------------------------------------------------
extern "C" __global__ void __launch_bounds__(NTHREADS, 1)
decoder_fused_kernel(
    const float* __restrict__ ih,     const float* __restrict__ plan,
    const float* __restrict__ gate,   const float* __restrict__ init_state,
    const float* __restrict__ Wp,     const float* __restrict__ bp,
    const float* __restrict__ Ws,     const float* __restrict__ bs,
    const float* __restrict__ Wqkv,   const float* __restrict__ bqkv,
    const float* __restrict__ Wo,     const float* __restrict__ bo,
    const float* __restrict__ g1,     const float* __restrict__ be1,
    const float* __restrict__ g2,     const float* __restrict__ be2,
    const float* __restrict__ W1,     const float* __restrict__ b1,
    const float* __restrict__ W2,     const float* __restrict__ b2,
    const float* __restrict__ Wd1,    const float* __restrict__ bd1,
    const float* __restrict__ Wd2,    const float* __restrict__ bd2,
    float* __restrict__ out)
{
    extern __shared__ float sm[];
    const int tid  = threadIdx.x;
    const int lane = tid & 31;
    const int w    = tid >> 5;
    const int wm = w >> 1, wn = w & 1;   // producer warp layout
    const int mg = w >> 2, ng = w & 3;   // consumer warp layout
    const int row0 = blockIdx.x * M_ROWS;

    const float* Wv = Wqkv + 2 * D_DIM * D_DIM;
    const float* bv = bqkv + 2 * D_DIM;

    // one-time parameter staging
    cpy(sm + WP_,  Wp,  1152, tid);
    cpy(sm + WS_,  Ws,  1152, tid);
    cpy(sm + BP_,  bp,   384, tid);
    cpy(sm + BS_,  bs,   384, tid);
    cpy(sm + BV_,  bv,   384, tid);
    cpy(sm + BO_,  bo,   384, tid);
    cpy(sm + B1_,  b1,  1024, tid);
    cpy(sm + B2_,  b2,   384, tid);
    cpy(sm + G1_,  g1,   384, tid);
    cpy(sm + BE1_, be1,  384, tid);
    cpy(sm + G2_,  g2,   384, tid);
    cpy(sm + BE2_, be2,  384, tid);
    cpy(sm + BD1_, bd1,   64, tid);
    cpy(sm + WD2_, Wd2,  192, tid);
    cpy(sm + BD2_, bd2,    3, tid);
    if (tid < 64)  sm[GATE_  + tid] = gate[row0 + tid];
    if (tid < 192) sm[STATE_ + tid] = init_state[(size_t)row0 * 3 + tid];

    const float* ihrow = ih + (size_t)row0 * D_DIM;

    for (int t = 0; t < T_STEPS; t++) {
        __syncthreads();   // state/xs from previous step fully written

        // load plan_t for the block's 64 rows
        if (tid < 192) {
            int r = tid / 3, j = tid - r * 3;
            sm[PLAN_ + tid] = plan[((size_t)(row0 + r) * T_STEPS + t) * 3 + j];
        }
        __syncthreads();

        // x = sf + pf*gate + init_hidden
#pragma unroll 4
        for (int i = 0; i < 96; i++) {
            int idx = tid + i * NTHREADS;
            int r = idx / D_DIM;
            int c = idx - r * D_DIM;
            float p0 = sm[PLAN_ + r * 3], p1 = sm[PLAN_ + r * 3 + 1], p2 = sm[PLAN_ + r * 3 + 2];
            float s0 = sm[STATE_ + r * 3], s1 = sm[STATE_ + r * 3 + 1], s2 = sm[STATE_ + r * 3 + 2];
            float pf = sm[BP_ + c] + p0 * sm[WP_ + c * 3] + p1 * sm[WP_ + c * 3 + 1] + p2 * sm[WP_ + c * 3 + 2];
            float sf = sm[BS_ + c] + s0 * sm[WS_ + c * 3] + s1 * sm[WS_ + c * 3 + 1] + s2 * sm[WS_ + c * 3 + 2];
            sm[XS + r * LDA + c] = sf + pf * sm[GATE_ + r] + ihrow[idx];
        }

        float acc[96];

        // ---- attention: attn = (x @ Wv^T + bv) @ Wo^T (+ bo via consumer? no:
        //      bo added through LN input below via... bo folded here:
#pragma unroll
        for (int i = 0; i < 96; i++) acc[i] = 0.f;
        for (int c = 0; c < 6; c++) {
            producer64<0, true>(Wv + (size_t)c * 64 * D_DIM, sm + BV_ + c * 64, sm, wm, wn, lane, tid);
            consumer384(Wo + c * 64, D_DIM, sm, acc, mg, ng, lane, tid);
        }
        // add bo into acc (once per output element; each acc elem owned by one thread)
#pragma unroll
        for (int s = 0; s < 6; s++)
#pragma unroll
            for (int mt = 0; mt < 2; mt++)
#pragma unroll
                for (int nt = 0; nt < 2; nt++)
#pragma unroll
                    for (int cc = 0; cc < 4; cc++) {
                        int n = s * 64 + ng * 16 + nt * 8 + ((lane & 3) << 1) + (cc & 1);
                        acc[((s * 2 + mt) * 2 + nt) * 4 + cc] += sm[BO_ + n];
                    }
        ln_epilogue(sm, acc, sm + G1_, sm + BE1_, mg, ng, lane);

        // ---- FF: h = relu(x @ W1^T + b1) @ W2^T + b2
#pragma unroll
        for (int i = 0; i < 96; i++) acc[i] = 0.f;
        for (int c = 0; c < 16; c++) {
            producer64<1, true>(W1 + (size_t)c * 64 * D_DIM, sm + B1_ + c * 64, sm, wm, wn, lane, tid);
            consumer384(W2 + c * 64, FF_DIM, sm, acc, mg, ng, lane, tid);
        }
#pragma unroll
        for (int s = 0; s < 6; s++)
#pragma unroll
            for (int mt = 0; mt < 2; mt++)
#pragma unroll
                for (int nt = 0; nt < 2; nt++)
#pragma unroll
                    for (int cc = 0; cc < 4; cc++) {
                        int n = s * 64 + ng * 16 + nt * 8 + ((lane & 3) << 1) + (cc & 1);
                        acc[((s * 2 + mt) * 2 + nt) * 4 + cc] += sm[B2_ + n];
                    }
        ln_epilogue(sm, acc, sm + G2_, sm + BE2_, mg, ng, lane);

        // ---- decoder: hid = elu(x @ Wd1^T + bd1) (fp32 in ych)
        producer64<2, false>(Wd1, sm + BD1_, sm, wm, wn, lane, tid);
        __syncthreads();

        // upd = hid @ Wd2^T + bd2 ; nxt = state + upd ; emit + carry
        if (tid < 192) {
            int r = tid / 3, i = tid - r * 3;
            float u = sm[BD2_ + i];
            const float* y  = sm + YCH + r * LDY;
            const float* w2 = sm + WD2_ + i * 64;
#pragma unroll 16
            for (int j = 0; j < 64; j++) u += y[j] * w2[j];
            float nxt = sm[STATE_ + r * 3 + i] + u;
            out[((size_t)(row0 + r) * T_STEPS + t) * 3 + i] = nxt;
            sm[STATE_ + r * 3 + i] = nxt;
        }
    }
}

// ---------------------------------------------------------------------------
// launch
// ---------------------------------------------------------------------------
extern "C" void kernel_launch(void* const* d_in, const int* in_sizes, int n_in,
                              void* d_out, int out_size)
{
    (void)in_sizes; (void)n_in; (void)out_size;
    cudaFuncSetAttribute(decoder_fused_kernel,
                         cudaFuncAttributeMaxDynamicSharedMemorySize, SMEM_BYTES);
    decoder_fused_kernel<<<B_TOTAL / M_ROWS, NTHREADS, SMEM_BYTES>>>(
        (const float*)d_in[0],  (const float*)d_in[1],  (const float*)d_in[2],
        (const float*)d_in[3],  (const float*)d_in[4],  (const float*)d_in[5],
        (const float*)d_in[6],  (const float*)d_in[7],  (const float*)d_in[8],
        (const float*)d_in[9],  (const float*)d_in[10], (const float*)d_in[11],
        (const float*)d_in[12], (const float*)d_in[13], (const float*)d_in[14],
        (const float*)d_in[15], (const float*)d_in[16], (const float*)d_in[17],
        (const float*)d_in[18], (const float*)d_in[19], (const float*)d_in[20],
        (const float*)d_in[21], (const float*)d_in[22], (const float*)d_in[23],
        (float*)d_out);
}

// round 6
// speedup vs baseline: 1.0433x; 1.0433x over previous
#include <cuda_runtime.h>
#include <cstdint>

// ---------------------------------------------------------------------------
// Fused recurrent decoder: B=32768, T=30, D=384, FF=1024, HID=64.
// One block = 64 rows, all 30 steps. TF32 mma.sync, cp.async double-buffered
// weight staging (raw fp32 -> HW tf32 truncation), decoder path kept RNA.
// ---------------------------------------------------------------------------

#define B_TOTAL   32768
#define T_STEPS   30
#define D_DIM     384
#define FF_DIM    1024
#define NTH       256

#define LDA   388   // xs stride  (388 % 32 == 4 -> conflict-free frags)
#define LDY   132   // ych stride (132 % 32 == 4)
#define LDSC  20    // consumer stage tile stride
#define LDSP  52    // producer stage tile stride

// shared memory float offsets
#define XS     0                 // 64*388 = 24832
#define YCH    24832             // 64*132 = 8448
#define DB0    33280             // 7680  (max(384*20, 128*52))
#define DB1    40960             // 7680
#define WP_    48640             // 1152
#define WS_    49792             // 1152
#define BP_    50944             // 384
#define BS_    51328             // 384
#define BV_    51712             // 384
#define BO_    52096             // 384
#define B1_    52480             // 1024
#define B2_    53504             // 384
#define G1_    53888             // 384
#define BE1_   54272             // 384
#define G2_    54656             // 384
#define BE2_   55040             // 384
#define BD1_   55424             // 64
#define WD2_   55488             // 192
#define BD2_   55680             // 4
#define GATE_  55684             // 64
#define STATE_ 55748             // 192
#define PLAN_  55940             // 192
#define RED_   56132             // 512 (float2[64][4])
#define SMEM_FLOATS 56644
#define SMEM_BYTES  (SMEM_FLOATS * 4)   // 226576 B

__device__ __forceinline__ uint32_t f2tf(float x) {
    uint32_t u;
    asm("cvt.rna.tf32.f32 %0, %1;" : "=r"(u) : "f"(x));
    return u;
}

__device__ __forceinline__ void mma8(float* c, uint32_t a0, uint32_t a1,
                                     uint32_t a2, uint32_t a3,
                                     uint32_t b0, uint32_t b1) {
    asm volatile(
        "mma.sync.aligned.m16n8k8.row.col.f32.tf32.tf32.f32 "
        "{%0,%1,%2,%3}, {%4,%5,%6,%7}, {%8,%9}, {%0,%1,%2,%3};"
        : "+f"(c[0]), "+f"(c[1]), "+f"(c[2]), "+f"(c[3])
        : "r"(a0), "r"(a1), "r"(a2), "r"(a3), "r"(b0), "r"(b1));
}

__device__ __forceinline__ void cp16(float* dst, const float* src) {
    uint32_t d = (uint32_t)__cvta_generic_to_shared(dst);
    asm volatile("cp.async.cg.shared.global [%0], [%1], 16;" :: "r"(d), "l"(src));
}
__device__ __forceinline__ void cp_commit() {
    asm volatile("cp.async.commit_group;" ::: "memory");
}
__device__ __forceinline__ void cp_wait0() {
    asm volatile("cp.async.wait_group 0;" ::: "memory");
}

// ---------------------------------------------------------------------------
// Producer (128-wide): ych[64 x 128] = ACT( xs[64x384] @ Wg[128 x 384]^T + b )
// Warp: pm = w>>2 (2 m16-tiles at pm*32+mt*16), pn = w&3 (4 n8-tiles j*32+pn*8).
// Weights staged via cp.async, 8 k-stages of 48, double buffered.
// Output RNA-rounded to tf32 bits.
// ---------------------------------------------------------------------------
template<int ACT>
__device__ __forceinline__ void producer128(
    const float* __restrict__ Wg, const float* __restrict__ bias,
    float* __restrict__ sm, int pm, int pn, int lane, int tid)
{
    float* xs  = sm + XS;
    float* ych = sm + YCH;

    float pacc[32];
#pragma unroll
    for (int i = 0; i < 32; i++) pacc[i] = 0.f;

    {   // prefetch stage 0
        float* buf = sm + DB0;
#pragma unroll
        for (int i = 0; i < 6; i++) {
            int q = tid + i * NTH;           // 0..1535 chunks of 16B
            int n = q / 12, kq = q - n * 12; // 128 rows x 12 chunks
            cp16(buf + n * LDSP + kq * 4, Wg + (size_t)n * D_DIM + kq * 4);
        }
        cp_commit();
    }

#pragma unroll 1
    for (int st = 0; st < 8; ++st) {
        float* buf = sm + ((st & 1) ? DB1 : DB0);
        cp_wait0();
        __syncthreads();
        if (st < 7) {
            float* nb = sm + ((st & 1) ? DB0 : DB1);
            const float* wsrc = Wg + (st + 1) * 48;
#pragma unroll
            for (int i = 0; i < 6; i++) {
                int q = tid + i * NTH;
                int n = q / 12, kq = q - n * 12;
                cp16(nb + n * LDSP + kq * 4, wsrc + (size_t)n * D_DIM + kq * 4);
            }
            cp_commit();
        }
#pragma unroll
        for (int k8 = 0; k8 < 6; k8++) {
            uint32_t a[2][4];
#pragma unroll
            for (int mt = 0; mt < 2; mt++) {
                const float* ap = xs + (pm * 32 + mt * 16 + (lane >> 2)) * LDA
                                     + st * 48 + k8 * 8 + (lane & 3);
                a[mt][0] = __float_as_uint(ap[0]);
                a[mt][1] = __float_as_uint(ap[8 * LDA]);
                a[mt][2] = __float_as_uint(ap[4]);
                a[mt][3] = __float_as_uint(ap[8 * LDA + 4]);
            }
#pragma unroll
            for (int j = 0; j < 4; j++) {
                const float* bp = buf + (j * 32 + pn * 8 + (lane >> 2)) * LDSP
                                      + k8 * 8 + (lane & 3);
                uint32_t b0 = __float_as_uint(bp[0]);
                uint32_t b1 = __float_as_uint(bp[4]);
#pragma unroll
                for (int mt = 0; mt < 2; mt++)
                    mma8(pacc + (mt * 4 + j) * 4,
                         a[mt][0], a[mt][1], a[mt][2], a[mt][3], b0, b1);
            }
        }
    }

    // epilogue: bias + activation + RNA tf32 round, write ych
#pragma unroll
    for (int mt = 0; mt < 2; mt++) {
        int r0 = pm * 32 + mt * 16 + (lane >> 2);
#pragma unroll
        for (int j = 0; j < 4; j++) {
            int n0 = j * 32 + pn * 8 + ((lane & 3) << 1);
            float bb0 = bias[n0], bb1 = bias[n0 + 1];
            float v[4];
            v[0] = pacc[(mt * 4 + j) * 4 + 0] + bb0;
            v[1] = pacc[(mt * 4 + j) * 4 + 1] + bb1;
            v[2] = pacc[(mt * 4 + j) * 4 + 2] + bb0;
            v[3] = pacc[(mt * 4 + j) * 4 + 3] + bb1;
#pragma unroll
            for (int cc = 0; cc < 4; cc++) {
                float x = v[cc];
                if (ACT == 1) x = fmaxf(x, 0.f);
                v[cc] = __uint_as_float(f2tf(x));
            }
            ych[r0 * LDY + n0]           = v[0];
            ych[r0 * LDY + n0 + 1]       = v[1];
            ych[(r0 + 8) * LDY + n0]     = v[2];
            ych[(r0 + 8) * LDY + n0 + 1] = v[3];
        }
    }
}

// ---------------------------------------------------------------------------
// Consumer: acc[64 x 384] += ych[64 x 128] @ Wc[384 n x 128 k-cols]^T
// Wbase = Wc + cblk*128 (column offset), row stride ldw.
// B staged full-n: 8 stages of [384 n x 16 k], double buffered.
// Warp: mg = w>>2 (2 m-tiles mg*32+mt*16), ng = w&3 (12 n-tiles j*32+ng*8).
// ---------------------------------------------------------------------------
__device__ __forceinline__ void consumer128(
    const float* __restrict__ Wc, int ldw, int cblk,
    float* __restrict__ sm, float (&acc)[96],
    int mg, int ng, int lane, int tid)
{
    float* ych = sm + YCH;
    const float* Wbase = Wc + cblk * 128;

    {   // prefetch stage 0
        float* buf = sm + DB0;
#pragma unroll
        for (int i = 0; i < 6; i++) {
            int q = tid + i * NTH;       // 0..1535; 384 rows x 4 chunks
            int n = q >> 2, kq = q & 3;
            cp16(buf + n * LDSC + kq * 4, Wbase + (size_t)n * ldw + kq * 4);
        }
        cp_commit();
    }

#pragma unroll 1
    for (int st = 0; st < 8; ++st) {
        float* buf = sm + ((st & 1) ? DB1 : DB0);
        cp_wait0();
        __syncthreads();
        if (st < 7) {
            float* nb = sm + ((st & 1) ? DB0 : DB1);
            const float* wsrc = Wbase + (st + 1) * 16;
#pragma unroll
            for (int i = 0; i < 6; i++) {
                int q = tid + i * NTH;
                int n = q >> 2, kq = q & 3;
                cp16(nb + n * LDSC + kq * 4, wsrc + (size_t)n * ldw + kq * 4);
            }
            cp_commit();
        }
#pragma unroll
        for (int k8 = 0; k8 < 2; k8++) {
            uint32_t a[2][4];
#pragma unroll
            for (int mt = 0; mt < 2; mt++) {
                const float* ap = ych + ((mg * 2 + mt) * 16 + (lane >> 2)) * LDY
                                      + st * 16 + k8 * 8 + (lane & 3);
                a[mt][0] = __float_as_uint(ap[0]);
                a[mt][1] = __float_as_uint(ap[8 * LDY]);
                a[mt][2] = __float_as_uint(ap[4]);
                a[mt][3] = __float_as_uint(ap[8 * LDY + 4]);
            }
#pragma unroll
            for (int j = 0; j < 12; j++) {
                const float* bp = buf + (j * 32 + ng * 8 + (lane >> 2)) * LDSC
                                      + k8 * 8 + (lane & 3);
                uint32_t b0 = __float_as_uint(bp[0]);
                uint32_t b1 = __float_as_uint(bp[4]);
                mma8(acc + (j * 2 + 0) * 4, a[0][0], a[0][1], a[0][2], a[0][3], b0, b1);
                mma8(acc + (j * 2 + 1) * 4, a[1][0], a[1][1], a[1][2], a[1][3], b0, b1);
            }
        }
    }
}

// ---------------------------------------------------------------------------
// LN epilogue: xs <- LN(xs + acc) * g + be
// ---------------------------------------------------------------------------
__device__ __forceinline__ void ln_epilogue(
    float* __restrict__ sm, float (&acc)[96],
    const float* __restrict__ g, const float* __restrict__ be,
    int mg, int ng, int lane)
{
    float*  xs  = sm + XS;
    float2* red = reinterpret_cast<float2*>(sm + RED_);

    float s4[4], q4[4];
#pragma unroll
    for (int i = 0; i < 4; i++) { s4[i] = 0.f; q4[i] = 0.f; }

#pragma unroll
    for (int j = 0; j < 12; j++)
#pragma unroll
        for (int mt = 0; mt < 2; mt++)
#pragma unroll
            for (int cc = 0; cc < 4; cc++) {
                int r = mg * 32 + mt * 16 + (lane >> 2) + ((cc >> 1) << 3);
                int n = j * 32 + ng * 8 + ((lane & 3) << 1) + (cc & 1);
                float v = xs[r * LDA + n] + acc[(j * 2 + mt) * 4 + cc];
                xs[r * LDA + n] = v;
                int ri = mt * 2 + (cc >> 1);
                s4[ri] += v;
                q4[ri] += v * v;
            }
#pragma unroll
    for (int d = 1; d < 4; d <<= 1)
#pragma unroll
        for (int i = 0; i < 4; i++) {
            s4[i] += __shfl_xor_sync(0xffffffffu, s4[i], d);
            q4[i] += __shfl_xor_sync(0xffffffffu, q4[i], d);
        }
    if ((lane & 3) == 0) {
#pragma unroll
        for (int i = 0; i < 4; i++) {
            int r = mg * 32 + (i >> 1) * 16 + (lane >> 2) + ((i & 1) << 3);
            red[r * 4 + ng] = make_float2(s4[i], q4[i]);
        }
    }
    __syncthreads();

#pragma unroll
    for (int i = 0; i < 4; i++) {
        int mt = i >> 1, h = i & 1;
        int r = mg * 32 + mt * 16 + (lane >> 2) + h * 8;
        float S = 0.f, Q = 0.f;
#pragma unroll
        for (int w = 0; w < 4; w++) { float2 tv = red[r * 4 + w]; S += tv.x; Q += tv.y; }
        float m   = S * (1.f / 384.f);
        float var = Q * (1.f / 384.f) - m * m;
        float rs  = rsqrtf(var + 1e-5f);
#pragma unroll
        for (int j = 0; j < 12; j++)
#pragma unroll
            for (int cc = 0; cc < 2; cc++) {
                int n = j * 32 + ng * 8 + ((lane & 3) << 1) + cc;
                float v = xs[r * LDA + n];
                xs[r * LDA + n] = (v - m) * rs * g[n] + be[n];
            }
    }
}

// ---------------------------------------------------------------------------
// Decoder producer (64-wide, RNA staging for state-path accuracy):
// ych[64 x 64] = elu( xs @ Wd1[64 x 384]^T + bd1 ), fp32 output.
// ---------------------------------------------------------------------------
__device__ __forceinline__ void producer_dec(
    const float* __restrict__ Wd1, const float* __restrict__ bias,
    float* __restrict__ sm, int wm, int wn, int lane, int tid)
{
    float* xs  = sm + XS;
    float* ych = sm + YCH;
    float* bt  = sm + DB0;

    float pacc[16];
#pragma unroll
    for (int i = 0; i < 16; i++) pacc[i] = 0.f;

#pragma unroll 1
    for (int st = 0; st < 8; st++) {
        __syncthreads();
#pragma unroll
        for (int i = 0; i < 3; i++) {
            int q = tid + i * NTH;           // 0..767; 64 rows x 12 chunks
            int n = q / 12, kq = q - n * 12;
            float4 v = *reinterpret_cast<const float4*>(Wd1 + (size_t)n * D_DIM + st * 48 + kq * 4);
            float4 w;
            w.x = __uint_as_float(f2tf(v.x));
            w.y = __uint_as_float(f2tf(v.y));
            w.z = __uint_as_float(f2tf(v.z));
            w.w = __uint_as_float(f2tf(v.w));
            *reinterpret_cast<float4*>(bt + n * LDSP + kq * 4) = w;
        }
        __syncthreads();
#pragma unroll
        for (int k8 = 0; k8 < 6; k8++) {
            const float* ap = xs + (wm * 16 + (lane >> 2)) * LDA + st * 48 + k8 * 8 + (lane & 3);
            uint32_t a0 = f2tf(ap[0]);
            uint32_t a1 = f2tf(ap[8 * LDA]);
            uint32_t a2 = f2tf(ap[4]);
            uint32_t a3 = f2tf(ap[8 * LDA + 4]);
#pragma unroll
            for (int tl = 0; tl < 4; tl++) {
                const float* bp = bt + (wn * 32 + tl * 8 + (lane >> 2)) * LDSP + k8 * 8 + (lane & 3);
                mma8(pacc + tl * 4, a0, a1, a2, a3,
                     __float_as_uint(bp[0]), __float_as_uint(bp[4]));
            }
        }
    }

    int r0 = wm * 16 + (lane >> 2);
#pragma unroll
    for (int tl = 0; tl < 4; tl++) {
        int n0 = wn * 32 + tl * 8 + ((lane & 3) << 1);
        float bb0 = bias[n0], bb1 = bias[n0 + 1];
        float v[4];
        v[0] = pacc[tl * 4 + 0] + bb0;
        v[1] = pacc[tl * 4 + 1] + bb1;
        v[2] = pacc[tl * 4 + 2] + bb0;
        v[3] = pacc[tl * 4 + 3] + bb1;
#pragma unroll
        for (int cc = 0; cc < 4; cc++) { float x = v[cc]; v[cc] = (x > 0.f) ? x : expm1f(x); }
        ych[r0 * LDY + n0]           = v[0];
        ych[r0 * LDY + n0 + 1]       = v[1];
        ych[(r0 + 8) * LDY + n0]     = v[2];
        ych[(r0 + 8) * LDY + n0 + 1] = v[3];
    }
}

__device__ __forceinline__ void cpy(float* __restrict__ dst,
                                    const float* __restrict__ src,
                                    int n, int tid)
{
    for (int i = tid; i < n; i += NTH) dst[i] = src[i];
}

// ---------------------------------------------------------------------------
// Main kernel
// ---------------------------------------------------------------------------
extern "C" __global__ void __launch_bounds__(NTH, 1)
decoder_fused_kernel(
    const float* __restrict__ ih,     const float* __restrict__ plan,
    const float* __restrict__ gate,   const float* __restrict__ init_state,
    const float* __restrict__ Wp,     const float* __restrict__ bp,
    const float* __restrict__ Ws,     const float* __restrict__ bs,
    const float* __restrict__ Wqkv,   const float* __restrict__ bqkv,
    const float* __restrict__ Wo,     const float* __restrict__ bo,
    const float* __restrict__ g1,     const float* __restrict__ be1,
    const float* __restrict__ g2,     const float* __restrict__ be2,
    const float* __restrict__ W1,     const float* __restrict__ b1,
    const float* __restrict__ W2,     const float* __restrict__ b2,
    const float* __restrict__ Wd1,    const float* __restrict__ bd1,
    const float* __restrict__ Wd2,    const float* __restrict__ bd2,
    float* __restrict__ out)
{
    extern __shared__ float sm[];
    const int tid  = threadIdx.x;
    const int lane = tid & 31;
    const int w    = tid >> 5;
    const int pm = w >> 2, pn = w & 3;   // producer128 layout
    const int mg = w >> 2, ng = w & 3;   // consumer layout
    const int wm = w >> 1, wn = w & 1;   // decoder producer layout
    const int row0 = blockIdx.x * 64;

    const float* Wv = Wqkv + 2 * D_DIM * D_DIM;
    const float* bv = bqkv + 2 * D_DIM;

    // one-time parameter staging
    cpy(sm + WP_,  Wp,  1152, tid);
    cpy(sm + WS_,  Ws,  1152, tid);
    cpy(sm + BP_,  bp,   384, tid);
    cpy(sm + BS_,  bs,   384, tid);
    cpy(sm + BV_,  bv,   384, tid);
    cpy(sm + BO_,  bo,   384, tid);
    cpy(sm + B1_,  b1,  1024, tid);
    cpy(sm + B2_,  b2,   384, tid);
    cpy(sm + G1_,  g1,   384, tid);
    cpy(sm + BE1_, be1,  384, tid);
    cpy(sm + G2_,  g2,   384, tid);
    cpy(sm + BE2_, be2,  384, tid);
    cpy(sm + BD1_, bd1,   64, tid);
    cpy(sm + WD2_, Wd2,  192, tid);
    cpy(sm + BD2_, bd2,    3, tid);
    if (tid < 64)  sm[GATE_  + tid] = gate[row0 + tid];
    if (tid < 192) sm[STATE_ + tid] = init_state[(size_t)row0 * 3 + tid];

    const float* ihrow = ih + (size_t)row0 * D_DIM;

    for (int t = 0; t < T_STEPS; t++) {
        __syncthreads();

        if (tid < 192) {
            int r = tid / 3, j = tid - r * 3;
            sm[PLAN_ + tid] = plan[((size_t)(row0 + r) * T_STEPS + t) * 3 + j];
        }
        __syncthreads();

        // x = sf + pf*gate + init_hidden
#pragma unroll 4
        for (int i = 0; i < 96; i++) {
            int idx = tid + i * NTH;
            int r = idx / D_DIM;
            int c = idx - r * D_DIM;
            float p0 = sm[PLAN_ + r * 3], p1 = sm[PLAN_ + r * 3 + 1], p2 = sm[PLAN_ + r * 3 + 2];
            float s0 = sm[STATE_ + r * 3], s1 = sm[STATE_ + r * 3 + 1], s2 = sm[STATE_ + r * 3 + 2];
            float pf = sm[BP_ + c] + p0 * sm[WP_ + c * 3] + p1 * sm[WP_ + c * 3 + 1] + p2 * sm[WP_ + c * 3 + 2];
            float sf = sm[BS_ + c] + s0 * sm[WS_ + c * 3] + s1 * sm[WS_ + c * 3 + 1] + s2 * sm[WS_ + c * 3 + 2];
            sm[XS + r * LDA + c] = sf + pf * sm[GATE_ + r] + ihrow[idx];
        }

        float acc[96];

        // ---- attention: attn = (x @ Wv^T + bv) @ Wo^T + bo
#pragma unroll
        for (int i = 0; i < 96; i++) acc[i] = 0.f;
        for (int c = 0; c < 3; c++) {
            producer128<0>(Wv + (size_t)c * 128 * D_DIM, sm + BV_ + c * 128, sm, pm, pn, lane, tid);
            consumer128(Wo, D_DIM, c, sm, acc, mg, ng, lane, tid);
        }
#pragma unroll
        for (int j = 0; j < 12; j++)
#pragma unroll
            for (int mt = 0; mt < 2; mt++)
#pragma unroll
                for (int cc = 0; cc < 4; cc++) {
                    int n = j * 32 + ng * 8 + ((lane & 3) << 1) + (cc & 1);
                    acc[(j * 2 + mt) * 4 + cc] += sm[BO_ + n];
                }
        ln_epilogue(sm, acc, sm + G1_, sm + BE1_, mg, ng, lane);

        // ---- FF: h = relu(x @ W1^T + b1) @ W2^T + b2
#pragma unroll
        for (int i = 0; i < 96; i++) acc[i] = 0.f;
        for (int c = 0; c < 8; c++) {
            producer128<1>(W1 + (size_t)c * 128 * D_DIM, sm + B1_ + c * 128, sm, pm, pn, lane, tid);
            consumer128(W2, FF_DIM, c, sm, acc, mg, ng, lane, tid);
        }
#pragma unroll
        for (int j = 0; j < 12; j++)
#pragma unroll
            for (int mt = 0; mt < 2; mt++)
#pragma unroll
                for (int cc = 0; cc < 4; cc++) {
                    int n = j * 32 + ng * 8 + ((lane & 3) << 1) + (cc & 1);
                    acc[(j * 2 + mt) * 4 + cc] += sm[B2_ + n];
                }
        ln_epilogue(sm, acc, sm + G2_, sm + BE2_, mg, ng, lane);

        // ---- decoder: hid = elu(x @ Wd1^T + bd1)  (fp32, RNA path)
        producer_dec(Wd1, sm + BD1_, sm, wm, wn, lane, tid);
        __syncthreads();

        // upd = hid @ Wd2^T + bd2 ; nxt = state + upd ; emit + carry
        if (tid < 192) {
            int r = tid / 3, i = tid - r * 3;
            float u = sm[BD2_ + i];
            const float* y  = sm + YCH + r * LDY;
            const float* w2 = sm + WD2_ + i * 64;
#pragma unroll 16
            for (int j = 0; j < 64; j++) u += y[j] * w2[j];
            float nxt = sm[STATE_ + r * 3 + i] + u;
            out[((size_t)(row0 + r) * T_STEPS + t) * 3 + i] = nxt;
            sm[STATE_ + r * 3 + i] = nxt;
        }
    }
}

// ---------------------------------------------------------------------------
// launch
// ---------------------------------------------------------------------------
extern "C" void kernel_launch(void* const* d_in, const int* in_sizes, int n_in,
                              void* d_out, int out_size)
{
    (void)in_sizes; (void)n_in; (void)out_size;
    cudaFuncSetAttribute(decoder_fused_kernel,
                         cudaFuncAttributeMaxDynamicSharedMemorySize, SMEM_BYTES);
    decoder_fused_kernel<<<B_TOTAL / 64, NTH, SMEM_BYTES>>>(
        (const float*)d_in[0],  (const float*)d_in[1],  (const float*)d_in[2],
        (const float*)d_in[3],  (const float*)d_in[4],  (const float*)d_in[5],
        (const float*)d_in[6],  (const float*)d_in[7],  (const float*)d_in[8],
        (const float*)d_in[9],  (const float*)d_in[10], (const float*)d_in[11],
        (const float*)d_in[12], (const float*)d_in[13], (const float*)d_in[14],
        (const float*)d_in[15], (const float*)d_in[16], (const float*)d_in[17],
        (const float*)d_in[18], (const float*)d_in[19], (const float*)d_in[20],
        (const float*)d_in[21], (const float*)d_in[22], (const float*)d_in[23],
        (float*)d_out);
}